// round 3
// baseline (speedup 1.0000x reference)
#include <cuda_runtime.h>
#include <cuda_bf16.h>

#define BATCH 16
#define DIM   48
#define HID   16
#define CH    8
#define HH    256
#define WW    256
#define TILE  32
#define HT    34      // tile + halo
#define PITCH 35      // padded smem row pitch (== 3 mod 32 -> conflict-free)

__constant__ float cW1[DIM*HID];
__constant__ float cB1[HID];
__constant__ float cGamma[CH];
__constant__ float cBeta[CH];
__constant__ float cDW[CH*9];
__constant__ float cDWB[CH];
__constant__ float cPW[CH*CH];
__constant__ float cPWB[CH];
__constant__ float cW2[CH*DIM];
__constant__ float cB2[DIM];

__device__ __forceinline__ float gelu_exact(float u) {
    // exact gelu: u * Phi(u)
    return u * normcdff(u);
}

// Front path for one token: x[48] -> gelu(gelu(x@W1+b1)) -> split -> x1[8], layernorm(x2)->n[8]
__device__ __forceinline__ void token_front(const float* __restrict__ xtok,
                                            float* __restrict__ x1,
                                            float* __restrict__ n) {
    float acc[HID];
    #pragma unroll
    for (int j = 0; j < HID; j++) acc[j] = cB1[j];

    const float4* xp4 = (const float4*)xtok;
    #pragma unroll
    for (int c4 = 0; c4 < DIM/4; c4++) {
        float4 v = xp4[c4];
        float xv0 = v.x, xv1 = v.y, xv2 = v.z, xv3 = v.w;
        #pragma unroll
        for (int j = 0; j < HID; j++) {
            acc[j] = fmaf(xv0, cW1[(c4*4+0)*HID + j], acc[j]);
            acc[j] = fmaf(xv1, cW1[(c4*4+1)*HID + j], acc[j]);
            acc[j] = fmaf(xv2, cW1[(c4*4+2)*HID + j], acc[j]);
            acc[j] = fmaf(xv3, cW1[(c4*4+3)*HID + j], acc[j]);
        }
    }

    #pragma unroll
    for (int j = 0; j < HID; j++) {
        float u = gelu_exact(acc[j]);
        acc[j] = gelu_exact(u);
    }

    #pragma unroll
    for (int j = 0; j < CH; j++) x1[j] = acc[j];

    // layernorm over acc[8..16)
    float m = 0.f;
    #pragma unroll
    for (int j = 0; j < CH; j++) m += acc[CH + j];
    m *= (1.0f/CH);
    float var = 0.f;
    #pragma unroll
    for (int j = 0; j < CH; j++) { float d = acc[CH+j] - m; var = fmaf(d, d, var); }
    var *= (1.0f/CH);
    float is = rsqrtf(var + 1e-5f);
    #pragma unroll
    for (int j = 0; j < CH; j++)
        n[j] = (acc[CH+j] - m) * is * cGamma[j] + cBeta[j];
}

__global__ void __launch_bounds__(256, 2)
fused_dclf_kernel(const float* __restrict__ x, float* __restrict__ out) {
    __shared__ float n_s[CH][HT*PITCH];

    const int b   = blockIdx.z;
    const int bx  = blockIdx.x * TILE;
    const int by  = blockIdx.y * TILE;
    const int tid = threadIdx.x;
    const int iy  = tid >> 3;           // 0..31
    const int ix0 = (tid & 7) << 2;     // 0,4,...,28
    const int gy  = by + iy;
    const int gx0 = bx + ix0;

    const float* xbase = x + (size_t)b * (DIM*HH*WW);

    float x1r[4][CH];

    // ---- phase 1a: interior pixels (this thread's quad) ----
    #pragma unroll
    for (int p = 0; p < 4; p++) {
        const float* xtok = xbase + (size_t)(gy * WW + gx0 + p) * DIM;
        float nv[CH];
        token_front(xtok, x1r[p], nv);
        int sidx = (iy+1)*PITCH + (ix0+p+1);
        #pragma unroll
        for (int c = 0; c < CH; c++) n_s[c][sidx] = nv[c];
    }

    // ---- phase 1b: halo ring (132 pixels, first 132 threads) ----
    if (tid < 132) {
        int hy, hx;
        if (tid < 34)       { hy = 0;   hx = tid;       }
        else if (tid < 68)  { hy = 33;  hx = tid - 34;  }
        else if (tid < 100) { hx = 0;   hy = tid - 67;  }   // 1..32
        else                { hx = 33;  hy = tid - 99;  }   // 1..32
        int gy2 = by + hy - 1;
        int gx2 = bx + hx - 1;
        float nv[CH];
        if (gy2 >= 0 && gy2 < HH && gx2 >= 0 && gx2 < WW) {
            float x1d[CH];
            token_front(xbase + (size_t)(gy2 * WW + gx2) * DIM, x1d, nv);
        } else {
            #pragma unroll
            for (int c = 0; c < CH; c++) nv[c] = 0.f;
        }
        int sidx = hy*PITCH + hx;
        #pragma unroll
        for (int c = 0; c < CH; c++) n_s[c][sidx] = nv[c];
    }

    __syncthreads();

    // ---- phase 2: dw-conv 3x3 + pw-conv 1x1 + gate ----
    float g[4][CH];
    #pragma unroll
    for (int p = 0; p < 4; p++) {
        const int base = (iy+1)*PITCH + (ix0+p+1);
        float nc[CH], sp[CH], chv[CH];
        #pragma unroll
        for (int c = 0; c < CH; c++) {
            nc[c] = n_s[c][base];
            float s = cDWB[c];
            #pragma unroll
            for (int dy = 0; dy < 3; dy++) {
                #pragma unroll
                for (int dx = 0; dx < 3; dx++) {
                    s = fmaf(cDW[c*9 + dy*3 + dx],
                             n_s[c][base + (dy-1)*PITCH + (dx-1)], s);
                }
            }
            sp[c] = s;
        }
        #pragma unroll
        for (int c = 0; c < CH; c++) {
            float t = cPWB[c];
            #pragma unroll
            for (int k = 0; k < CH; k++) t = fmaf(cPW[c*CH + k], nc[k], t);
            chv[c] = t;
        }
        #pragma unroll
        for (int c = 0; c < CH; c++) g[p][c] = x1r[p][c] * (sp[c] * chv[c]);
    }

    // ---- phase 3: back GEMM g[8] @ W2[8x48] + b2, channel-planar float4 stores ----
    #pragma unroll
    for (int o = 0; o < DIM; o++) {
        float vv[4];
        #pragma unroll
        for (int p = 0; p < 4; p++) {
            float s = cB2[o];
            #pragma unroll
            for (int j = 0; j < CH; j++) s = fmaf(g[p][j], cW2[j*DIM + o], s);
            vv[p] = s;
        }
        float4 v4 = make_float4(vv[0], vv[1], vv[2], vv[3]);
        *(float4*)(out + (((size_t)b*DIM + o)*HH + gy)*WW + gx0) = v4;
    }
}

extern "C" void kernel_launch(void* const* d_in, const int* in_sizes, int n_in,
                              void* d_out, int out_size) {
    // weights -> constant memory (device-to-device, graph-capturable)
    cudaMemcpyToSymbolAsync(cW1,    d_in[1],  sizeof(cW1),    0, cudaMemcpyDeviceToDevice, 0);
    cudaMemcpyToSymbolAsync(cB1,    d_in[2],  sizeof(cB1),    0, cudaMemcpyDeviceToDevice, 0);
    cudaMemcpyToSymbolAsync(cGamma, d_in[3],  sizeof(cGamma), 0, cudaMemcpyDeviceToDevice, 0);
    cudaMemcpyToSymbolAsync(cBeta,  d_in[4],  sizeof(cBeta),  0, cudaMemcpyDeviceToDevice, 0);
    cudaMemcpyToSymbolAsync(cDW,    d_in[5],  sizeof(cDW),    0, cudaMemcpyDeviceToDevice, 0);
    cudaMemcpyToSymbolAsync(cDWB,   d_in[6],  sizeof(cDWB),   0, cudaMemcpyDeviceToDevice, 0);
    cudaMemcpyToSymbolAsync(cPW,    d_in[7],  sizeof(cPW),    0, cudaMemcpyDeviceToDevice, 0);
    cudaMemcpyToSymbolAsync(cPWB,   d_in[8],  sizeof(cPWB),   0, cudaMemcpyDeviceToDevice, 0);
    cudaMemcpyToSymbolAsync(cW2,    d_in[9],  sizeof(cW2),    0, cudaMemcpyDeviceToDevice, 0);
    cudaMemcpyToSymbolAsync(cB2,    d_in[10], sizeof(cB2),    0, cudaMemcpyDeviceToDevice, 0);

    dim3 grid(WW/TILE, HH/TILE, BATCH);   // (8, 8, 16)
    fused_dclf_kernel<<<grid, 256>>>((const float*)d_in[0], (float*)d_out);
}

// round 4
// speedup vs baseline: 1.2698x; 1.2698x over previous
#include <cuda_runtime.h>
#include <cuda_bf16.h>

#define BATCH 16
#define DIM   48
#define HID   16
#define CH    8
#define HH    256
#define WW    256
#define TILE  32
#define HT    34      // tile + halo
#define PITCH 35      // padded smem row pitch (== 3 mod 32 -> conflict-free)

__constant__ float cW1[DIM*HID];
__constant__ float cB1[HID];
__constant__ float cGamma[CH];
__constant__ float cBeta[CH];
__constant__ float cDW[CH*9];
__constant__ float cDWB[CH];
__constant__ float cPW[CH*CH];
__constant__ float cPWB[CH];
__constant__ float cW2[CH*DIM];
__constant__ float cB2[DIM];

// ---------------- MUFU-free math ----------------

// e^y for y in [-90, 0]; bit-trick 2^n * degree-5 poly on [-0.5,0.5]. rel err ~2e-6.
__device__ __forceinline__ float expf_nomufu(float y) {
    float t = y * 1.44269504f;              // log2(e)
    float f = t + 12582912.0f;              // round-to-nearest via magic const (1.5*2^23)
    int   i = __float_as_int(f);
    float r = t - (f - 12582912.0f);        // r in [-0.5, 0.5]
    // 2^r Taylor (deg 5): 1 + r*ln2 + r^2 ln2^2/2 + ...
    float p = fmaf(r, fmaf(r, fmaf(r, fmaf(r, fmaf(r, 0.0013333558f, 0.0096181291f),
                    0.0555041087f), 0.2402265070f), 0.6931471806f), 1.0f);
    float scale = __int_as_float(((i - 0x4B400000) << 23) + 0x3F800000);
    return p * scale;
}

// 1/y for y in [0.5, 8]; bit-trick seed + 3 Newton steps. rel err << 1e-6.
__device__ __forceinline__ float rcp_nomufu(float y) {
    float r = __int_as_float(0x7EF311C3 - __float_as_int(y));
    r = r * fmaf(-y, r, 2.0f);
    r = r * fmaf(-y, r, 2.0f);
    r = r * fmaf(-y, r, 2.0f);
    return r;
}

// exact-accuracy gelu via A&S 7.1.26 erf (|eps| <= 1.5e-7), zero MUFU ops.
__device__ __forceinline__ float gelu_fast(float u) {
    float x = fabsf(u) * 0.70710678118f;            // |u|/sqrt(2)
    float k = rcp_nomufu(fmaf(0.3275911f, x, 1.0f));
    float e = expf_nomufu(-x * x);
    // 0.5*(a1 k + a2 k^2 + a3 k^3 + a4 k^4 + a5 k^5), a_i pre-halved
    float poly = k * fmaf(k, fmaf(k, fmaf(k, fmaf(k, 0.5307027145f, -0.7265760135f),
                      0.7107068705f), -0.142248368f), 0.127414796f);
    float s = poly * e;                              // 0.5*erfc(x)
    float Phi = (u >= 0.0f) ? (1.0f - s) : s;
    return u * Phi;
}

// ---------------- single-token front (halo path) ----------------
__device__ __forceinline__ void token_front(const float* __restrict__ xtok,
                                            float* __restrict__ x1,
                                            float* __restrict__ n) {
    float acc[HID];
    #pragma unroll
    for (int j = 0; j < HID; j++) acc[j] = cB1[j];

    const float4* xp4 = (const float4*)xtok;
    #pragma unroll
    for (int c4 = 0; c4 < DIM/4; c4++) {
        float4 v = xp4[c4];
        #pragma unroll
        for (int j = 0; j < HID; j++) {
            acc[j] = fmaf(v.x, cW1[(c4*4+0)*HID + j],
                     fmaf(v.y, cW1[(c4*4+1)*HID + j],
                     fmaf(v.z, cW1[(c4*4+2)*HID + j],
                     fmaf(v.w, cW1[(c4*4+3)*HID + j], acc[j]))));
        }
    }

    #pragma unroll
    for (int j = 0; j < HID; j++) acc[j] = gelu_fast(gelu_fast(acc[j]));

    #pragma unroll
    for (int j = 0; j < CH; j++) x1[j] = acc[j];

    float m = 0.f;
    #pragma unroll
    for (int j = 0; j < CH; j++) m += acc[CH + j];
    m *= (1.0f/CH);
    float var = 0.f;
    #pragma unroll
    for (int j = 0; j < CH; j++) { float d = acc[CH+j] - m; var = fmaf(d, d, var); }
    var *= (1.0f/CH);
    float is = rsqrtf(var + 1e-5f);
    #pragma unroll
    for (int j = 0; j < CH; j++)
        n[j] = (acc[CH+j] - m) * is * cGamma[j] + cBeta[j];
}

__global__ void __launch_bounds__(256, 2)
fused_dclf_kernel(const float* __restrict__ x, float* __restrict__ out) {
    __shared__ float n_s[CH][HT*PITCH];

    const int b   = blockIdx.z;
    const int bx  = blockIdx.x * TILE;
    const int by  = blockIdx.y * TILE;
    const int tid = threadIdx.x;
    const int iy  = tid >> 3;           // 0..31
    const int ix0 = (tid & 7) << 2;     // 0,4,...,28
    const int gy  = by + iy;
    const int gx0 = bx + ix0;

    const float* xbase = x + (size_t)b * (DIM*HH*WW);

    float x1r[4][CH];

    // ---- phase 1a: interior quad, 4 pixels THROUGH THE GEMM TOGETHER ----
    // (weight loaded once per (c,j), feeds 4 FMAs -> 4x less constant-port traffic)
    {
        float acc[4][HID];
        #pragma unroll
        for (int p = 0; p < 4; p++)
            #pragma unroll
            for (int j = 0; j < HID; j++) acc[p][j] = cB1[j];

        const float4* xp4 = (const float4*)(xbase + (size_t)(gy * WW + gx0) * DIM);
        // pixels are x-adjacent: pixel p's float4 c4 is xp4[p*(DIM/4) + c4]

        #pragma unroll
        for (int c4 = 0; c4 < DIM/4; c4++) {
            float4 xv[4];
            #pragma unroll
            for (int p = 0; p < 4; p++) xv[p] = xp4[p*(DIM/4) + c4];
            #pragma unroll
            for (int j = 0; j < HID; j++) {
                const float w0 = cW1[(c4*4+0)*HID + j];
                const float w1 = cW1[(c4*4+1)*HID + j];
                const float w2 = cW1[(c4*4+2)*HID + j];
                const float w3 = cW1[(c4*4+3)*HID + j];
                #pragma unroll
                for (int p = 0; p < 4; p++) {
                    acc[p][j] = fmaf(xv[p].x, w0,
                                fmaf(xv[p].y, w1,
                                fmaf(xv[p].z, w2,
                                fmaf(xv[p].w, w3, acc[p][j]))));
                }
            }
        }

        #pragma unroll
        for (int p = 0; p < 4; p++) {
            #pragma unroll
            for (int j = 0; j < HID; j++) acc[p][j] = gelu_fast(gelu_fast(acc[p][j]));

            #pragma unroll
            for (int j = 0; j < CH; j++) x1r[p][j] = acc[p][j];

            float m = 0.f;
            #pragma unroll
            for (int j = 0; j < CH; j++) m += acc[p][CH + j];
            m *= (1.0f/CH);
            float var = 0.f;
            #pragma unroll
            for (int j = 0; j < CH; j++) { float d = acc[p][CH+j] - m; var = fmaf(d, d, var); }
            var *= (1.0f/CH);
            float is = rsqrtf(var + 1e-5f);

            int sidx = (iy+1)*PITCH + (ix0+p+1);
            #pragma unroll
            for (int c = 0; c < CH; c++)
                n_s[c][sidx] = (acc[p][CH+c] - m) * is * cGamma[c] + cBeta[c];
        }
    }

    // ---- phase 1b: halo ring (132 pixels, first 132 threads) ----
    if (tid < 132) {
        int hy, hx;
        if (tid < 34)       { hy = 0;   hx = tid;       }
        else if (tid < 68)  { hy = 33;  hx = tid - 34;  }
        else if (tid < 100) { hx = 0;   hy = tid - 67;  }   // 1..32
        else                { hx = 33;  hy = tid - 99;  }   // 1..32
        int gy2 = by + hy - 1;
        int gx2 = bx + hx - 1;
        float nv[CH];
        if (gy2 >= 0 && gy2 < HH && gx2 >= 0 && gx2 < WW) {
            float x1d[CH];
            token_front(xbase + (size_t)(gy2 * WW + gx2) * DIM, x1d, nv);
        } else {
            #pragma unroll
            for (int c = 0; c < CH; c++) nv[c] = 0.f;
        }
        int sidx = hy*PITCH + hx;
        #pragma unroll
        for (int c = 0; c < CH; c++) n_s[c][sidx] = nv[c];
    }

    __syncthreads();

    // ---- phase 2: dw-conv 3x3 + pw-conv 1x1 + gate ----
    float g[4][CH];
    #pragma unroll
    for (int p = 0; p < 4; p++) {
        const int base = (iy+1)*PITCH + (ix0+p+1);
        float nc[CH], sp[CH], chv[CH];
        #pragma unroll
        for (int c = 0; c < CH; c++) {
            nc[c] = n_s[c][base];
            float s = cDWB[c];
            #pragma unroll
            for (int dy = 0; dy < 3; dy++) {
                #pragma unroll
                for (int dx = 0; dx < 3; dx++) {
                    s = fmaf(cDW[c*9 + dy*3 + dx],
                             n_s[c][base + (dy-1)*PITCH + (dx-1)], s);
                }
            }
            sp[c] = s;
        }
        #pragma unroll
        for (int c = 0; c < CH; c++) {
            float t = cPWB[c];
            #pragma unroll
            for (int k = 0; k < CH; k++) t = fmaf(cPW[c*CH + k], nc[k], t);
            chv[c] = t;
        }
        #pragma unroll
        for (int c = 0; c < CH; c++) g[p][c] = x1r[p][c] * (sp[c] * chv[c]);
    }

    // ---- phase 3: back GEMM g[8] @ W2[8x48] + b2, channel-planar float4 stores ----
    #pragma unroll
    for (int o = 0; o < DIM; o++) {
        float vv[4];
        #pragma unroll
        for (int p = 0; p < 4; p++) {
            float s = cB2[o];
            #pragma unroll
            for (int j = 0; j < CH; j++) s = fmaf(g[p][j], cW2[j*DIM + o], s);
            vv[p] = s;
        }
        float4 v4 = make_float4(vv[0], vv[1], vv[2], vv[3]);
        *(float4*)(out + (((size_t)b*DIM + o)*HH + gy)*WW + gx0) = v4;
    }
}

extern "C" void kernel_launch(void* const* d_in, const int* in_sizes, int n_in,
                              void* d_out, int out_size) {
    // weights -> constant memory (device-to-device, graph-capturable)
    cudaMemcpyToSymbolAsync(cW1,    d_in[1],  sizeof(cW1),    0, cudaMemcpyDeviceToDevice, 0);
    cudaMemcpyToSymbolAsync(cB1,    d_in[2],  sizeof(cB1),    0, cudaMemcpyDeviceToDevice, 0);
    cudaMemcpyToSymbolAsync(cGamma, d_in[3],  sizeof(cGamma), 0, cudaMemcpyDeviceToDevice, 0);
    cudaMemcpyToSymbolAsync(cBeta,  d_in[4],  sizeof(cBeta),  0, cudaMemcpyDeviceToDevice, 0);
    cudaMemcpyToSymbolAsync(cDW,    d_in[5],  sizeof(cDW),    0, cudaMemcpyDeviceToDevice, 0);
    cudaMemcpyToSymbolAsync(cDWB,   d_in[6],  sizeof(cDWB),   0, cudaMemcpyDeviceToDevice, 0);
    cudaMemcpyToSymbolAsync(cPW,    d_in[7],  sizeof(cPW),    0, cudaMemcpyDeviceToDevice, 0);
    cudaMemcpyToSymbolAsync(cPWB,   d_in[8],  sizeof(cPWB),   0, cudaMemcpyDeviceToDevice, 0);
    cudaMemcpyToSymbolAsync(cW2,    d_in[9],  sizeof(cW2),    0, cudaMemcpyDeviceToDevice, 0);
    cudaMemcpyToSymbolAsync(cB2,    d_in[10], sizeof(cB2),    0, cudaMemcpyDeviceToDevice, 0);

    dim3 grid(WW/TILE, HH/TILE, BATCH);   // (8, 8, 16)
    fused_dclf_kernel<<<grid, 256>>>((const float*)d_in[0], (float*)d_out);
}

// round 5
// speedup vs baseline: 1.4659x; 1.1544x over previous
#include <cuda_runtime.h>
#include <cuda_bf16.h>

#define BATCH 16
#define DIM   48
#define HID   16
#define CH    8
#define HH    256
#define WW    256
#define TILE  32
#define HT    34      // tile + halo
#define PITCH 35      // padded smem row pitch (== 3 mod 32 -> conflict-free)

__constant__ float cW1[DIM*HID];
__constant__ float cB1[HID];
__constant__ float cGamma[CH];
__constant__ float cBeta[CH];
__constant__ float cDW[CH*9];
__constant__ float cDWB[CH];
__constant__ float cPW[CH*CH];
__constant__ float cPWB[CH];
__constant__ float cW2[CH*DIM];
__constant__ float cB2[DIM];

// ---------------- MUFU-free exact GELU ----------------
// A&S 7.1.26 erf (|eps|<=1.5e-7) with bit-trick exp (2^n * deg-5 poly)
// and bit-trick rcp (seed + 2 Newton). Zero MUFU ops; fma/alu pipes only.
__device__ __forceinline__ float gelu_fast(float u) {
    // t = -x^2 * log2(e), x = |u|/sqrt(2)  ->  t = u*u * (-0.5*log2(e))
    float t = u * u * -0.72134752044f;
    float f = t + 12582912.0f;                       // round via magic const
    int   i = __float_as_int(f);
    float r = t - (f - 12582912.0f);                 // r in [-0.5, 0.5]
    float p = fmaf(r, fmaf(r, fmaf(r, fmaf(r, fmaf(r, 0.0013333558f, 0.0096181291f),
                    0.0555041087f), 0.2402265070f), 0.6931471806f), 1.0f);
    float e = p * __int_as_float(((i - 0x4B400000) << 23) + 0x3F800000);  // e^{-x^2}
    // k = 1/(1 + 0.3275911*x) = 1/(1 + 0.23164190*|u|)
    float d = fmaf(fabsf(u), 0.23164190f, 1.0f);
    float k = __int_as_float(0x7EF311C3 - __float_as_int(d));
    k = k * fmaf(-d, k, 2.0f);
    k = k * fmaf(-d, k, 2.0f);
    // 0.5*(a1 k + ... + a5 k^5), coeffs pre-halved
    float poly = k * fmaf(k, fmaf(k, fmaf(k, fmaf(k, 0.5307027145f, -0.7265760135f),
                      0.7107068705f), -0.142248368f), 0.127414796f);
    float s   = poly * e;                            // 0.5*erfc(x), in (0, 0.5]
    float Phi = 0.5f + copysignf(0.5f - s, u);
    return u * Phi;
}

// ---------------- single-token front (halo path), weights from smem ----------------
__device__ __forceinline__ void token_front(const float* __restrict__ xtok,
                                            const float* __restrict__ sW1,
                                            float* __restrict__ n) {
    float acc[HID];
    #pragma unroll
    for (int j = 0; j < HID; j++) acc[j] = cB1[j];

    const float4* xp4 = (const float4*)xtok;
    #pragma unroll
    for (int c4 = 0; c4 < DIM/4; c4++) {
        float4 v = xp4[c4];
        #pragma unroll
        for (int j = 0; j < HID; j++) {
            float w0 = sW1[(c4*4+0)*HID + j];
            float w1 = sW1[(c4*4+1)*HID + j];
            float w2 = sW1[(c4*4+2)*HID + j];
            float w3 = sW1[(c4*4+3)*HID + j];
            float a = acc[j];
            a = fmaf(v.x, w0, a);
            a = fmaf(v.y, w1, a);
            a = fmaf(v.z, w2, a);
            a = fmaf(v.w, w3, a);
            acc[j] = a;
        }
    }

    #pragma unroll
    for (int j = CH; j < HID; j++) acc[j] = gelu_fast(gelu_fast(acc[j]));

    float m = 0.f;
    #pragma unroll
    for (int j = 0; j < CH; j++) m += acc[CH + j];
    m *= (1.0f/CH);
    float var = 0.f;
    #pragma unroll
    for (int j = 0; j < CH; j++) { float dd = acc[CH+j] - m; var = fmaf(dd, dd, var); }
    var *= (1.0f/CH);
    float is = rsqrtf(var + 1e-5f);
    #pragma unroll
    for (int j = 0; j < CH; j++)
        n[j] = (acc[CH+j] - m) * is * cGamma[j] + cBeta[j];
}

__global__ void __launch_bounds__(256, 3)
fused_dclf_kernel(const float* __restrict__ x, float* __restrict__ out) {
    __shared__ float n_s[CH][HT*PITCH];   // 38080 B
    __shared__ float sW1[DIM*HID];        //  3072 B
    __shared__ float sW2[CH*DIM];         //  1536 B

    const int b   = blockIdx.z;
    const int bx  = blockIdx.x * TILE;
    const int by  = blockIdx.y * TILE;
    const int tid = threadIdx.x;
    const int iy  = tid >> 3;           // 0..31
    const int ix0 = (tid & 7) << 2;     // 0,4,...,28
    const int gy  = by + iy;
    const int gx0 = bx + ix0;

    // ---- stage weights: constant -> shared (LDS floor 2 vs LDC floor 8) ----
    #pragma unroll
    for (int i = 0; i < 3; i++) sW1[tid + 256*i] = cW1[tid + 256*i];
    if (tid < 128) {
        #pragma unroll
        for (int i = 0; i < 3; i++) sW2[tid + 128*i] = cW2[tid + 128*i];
    }
    __syncthreads();

    const float* xbase = x + (size_t)b * (DIM*HH*WW);

    float x1r[4][CH];

    // ---- phase 1a: interior quad as TWO passes of 2 pixels (cuts live regs) ----
    #pragma unroll
    for (int pass = 0; pass < 2; pass++) {
        const float4* xp = (const float4*)(xbase + (size_t)(gy * WW + gx0 + 2*pass) * DIM);

        float acc0[HID], acc1[HID];
        #pragma unroll
        for (int j = 0; j < HID; j++) { float bj = cB1[j]; acc0[j] = bj; acc1[j] = bj; }

        #pragma unroll
        for (int c4 = 0; c4 < DIM/4; c4++) {
            float4 a = xp[c4];
            float4 c = xp[DIM/4 + c4];
            #pragma unroll
            for (int j = 0; j < HID; j++) {
                float w0 = sW1[(c4*4+0)*HID + j];
                float w1 = sW1[(c4*4+1)*HID + j];
                float w2 = sW1[(c4*4+2)*HID + j];
                float w3 = sW1[(c4*4+3)*HID + j];
                float s0 = acc0[j], s1 = acc1[j];
                s0 = fmaf(a.x, w0, s0);   s1 = fmaf(c.x, w0, s1);
                s0 = fmaf(a.y, w1, s0);   s1 = fmaf(c.y, w1, s1);
                s0 = fmaf(a.z, w2, s0);   s1 = fmaf(c.z, w2, s1);
                s0 = fmaf(a.w, w3, s0);   s1 = fmaf(c.w, w3, s1);
                acc0[j] = s0; acc1[j] = s1;
            }
        }

        #pragma unroll
        for (int h = 0; h < 2; h++) {
            float* acc = h ? acc1 : acc0;
            const int p = 2*pass + h;

            #pragma unroll
            for (int j = 0; j < HID; j++) acc[j] = gelu_fast(gelu_fast(acc[j]));

            #pragma unroll
            for (int j = 0; j < CH; j++) x1r[p][j] = acc[j];

            float m = 0.f;
            #pragma unroll
            for (int j = 0; j < CH; j++) m += acc[CH + j];
            m *= (1.0f/CH);
            float var = 0.f;
            #pragma unroll
            for (int j = 0; j < CH; j++) { float dd = acc[CH+j] - m; var = fmaf(dd, dd, var); }
            var *= (1.0f/CH);
            float is = rsqrtf(var + 1e-5f);

            const int sidx = (iy+1)*PITCH + (ix0+p+1);
            #pragma unroll
            for (int c = 0; c < CH; c++)
                n_s[c][sidx] = (acc[CH+c] - m) * is * cGamma[c] + cBeta[c];
        }
    }

    // ---- phase 1b: halo ring (132 pixels, first 132 threads) ----
    if (tid < 132) {
        int hy, hx;
        if (tid < 34)       { hy = 0;   hx = tid;       }
        else if (tid < 68)  { hy = 33;  hx = tid - 34;  }
        else if (tid < 100) { hx = 0;   hy = tid - 67;  }   // 1..32
        else                { hx = 33;  hy = tid - 99;  }   // 1..32
        int gy2 = by + hy - 1;
        int gx2 = bx + hx - 1;
        float nv[CH];
        if (gy2 >= 0 && gy2 < HH && gx2 >= 0 && gx2 < WW) {
            token_front(xbase + (size_t)(gy2 * WW + gx2) * DIM, sW1, nv);
        } else {
            #pragma unroll
            for (int c = 0; c < CH; c++) nv[c] = 0.f;
        }
        int sidx = hy*PITCH + hx;
        #pragma unroll
        for (int c = 0; c < CH; c++) n_s[c][sidx] = nv[c];
    }

    __syncthreads();

    // ---- phase 2: dw-conv 3x3 + pw-conv 1x1 + gate (g overwrites x1r in place) ----
    #pragma unroll
    for (int p = 0; p < 4; p++) {
        const int base = (iy+1)*PITCH + (ix0+p+1);
        float nc[CH], sp[CH];
        #pragma unroll
        for (int c = 0; c < CH; c++) {
            nc[c] = n_s[c][base];
            float s = cDWB[c];
            #pragma unroll
            for (int dy = 0; dy < 3; dy++) {
                #pragma unroll
                for (int dx = 0; dx < 3; dx++) {
                    s = fmaf(cDW[c*9 + dy*3 + dx],
                             n_s[c][base + (dy-1)*PITCH + (dx-1)], s);
                }
            }
            sp[c] = s;
        }
        #pragma unroll
        for (int c = 0; c < CH; c++) {
            float t = cPWB[c];
            #pragma unroll
            for (int k = 0; k < CH; k++) t = fmaf(cPW[c*CH + k], nc[k], t);
            x1r[p][c] *= sp[c] * t;     // g = x1 * (sp * ch)
        }
    }

    // ---- phase 3: back GEMM g[8] @ W2[8x48] + b2, channel-planar float4 stores ----
    float* outb = out + (((size_t)b*DIM)*HH + gy)*WW + gx0;
    #pragma unroll
    for (int o = 0; o < DIM; o++) {
        float w[CH];
        #pragma unroll
        for (int j = 0; j < CH; j++) w[j] = sW2[j*DIM + o];
        float vv[4];
        #pragma unroll
        for (int p = 0; p < 4; p++) {
            float s = cB2[o];
            #pragma unroll
            for (int j = 0; j < CH; j++) s = fmaf(x1r[p][j], w[j], s);
            vv[p] = s;
        }
        *(float4*)(outb + (size_t)o*HH*WW) = make_float4(vv[0], vv[1], vv[2], vv[3]);
    }
}

extern "C" void kernel_launch(void* const* d_in, const int* in_sizes, int n_in,
                              void* d_out, int out_size) {
    // weights -> constant memory (device-to-device, graph-capturable)
    cudaMemcpyToSymbolAsync(cW1,    d_in[1],  sizeof(cW1),    0, cudaMemcpyDeviceToDevice, 0);
    cudaMemcpyToSymbolAsync(cB1,    d_in[2],  sizeof(cB1),    0, cudaMemcpyDeviceToDevice, 0);
    cudaMemcpyToSymbolAsync(cGamma, d_in[3],  sizeof(cGamma), 0, cudaMemcpyDeviceToDevice, 0);
    cudaMemcpyToSymbolAsync(cBeta,  d_in[4],  sizeof(cBeta),  0, cudaMemcpyDeviceToDevice, 0);
    cudaMemcpyToSymbolAsync(cDW,    d_in[5],  sizeof(cDW),    0, cudaMemcpyDeviceToDevice, 0);
    cudaMemcpyToSymbolAsync(cDWB,   d_in[6],  sizeof(cDWB),   0, cudaMemcpyDeviceToDevice, 0);
    cudaMemcpyToSymbolAsync(cPW,    d_in[7],  sizeof(cPW),    0, cudaMemcpyDeviceToDevice, 0);
    cudaMemcpyToSymbolAsync(cPWB,   d_in[8],  sizeof(cPWB),   0, cudaMemcpyDeviceToDevice, 0);
    cudaMemcpyToSymbolAsync(cW2,    d_in[9],  sizeof(cW2),    0, cudaMemcpyDeviceToDevice, 0);
    cudaMemcpyToSymbolAsync(cB2,    d_in[10], sizeof(cB2),    0, cudaMemcpyDeviceToDevice, 0);

    dim3 grid(WW/TILE, HH/TILE, BATCH);   // (8, 8, 16)
    fused_dclf_kernel<<<grid, 256>>>((const float*)d_in[0], (float*)d_out);
}